// round 12
// baseline (speedup 1.0000x reference)
#include <cuda_runtime.h>
#include <cuda_bf16.h>
#include <cuda_fp8.h>
#include <cstdint>
#include <math.h>

// NTXentLoss via mma.sync FP8 (e4m3) GEMM, symmetric upper-triangular tiles.
// Round 12: bf16 HMMA issue floor reached (~60us); switch to m16n8k32 e4m3
// (2x MACs/instr). Z = normalize(reps) * sqrt(2*log2e) quantized to e4m3;
// epilogue is bare ex2. pos stays exact fp32. Strip-mined 4 J-tiles/CTA.

#define M_TOTAL 8192
#define N_HALF  4096
#define DDIM    256
#define RT      128
#define NT64    (M_TOTAL / RT)           // 64 tile blocks
#define STRIP   4
#define NTH     512
#define SMS_B   272                      // fp8 tile row stride: 256 B + 16 pad
#define SQRT_L2E2 1.6986441f             // sqrt(2/ln2); dot = 2*log2e*sim

// Scratch (__device__ globals: allocation-free rule)
__device__ uint8_t g_Z[M_TOTAL * DDIM];             // normalized*s, e4m3 bytes
__device__ float g_pos[M_TOTAL];                    // 2*sim[i, pair] (fp32)
__device__ float g_spart[NT64][M_TOTAL];            // partial sums, slot-unique
__device__ float g_red[32];                         // loss block partials
__device__ unsigned int g_ctr;                      // loss completion counter

// smem layout (bytes)
#define SM_A    0
#define SM_B0   (RT * SMS_B)             // 34816
#define SM_B1   (2 * RT * SMS_B)         // 69632
#define SM_CSC  (3 * RT * SMS_B)         // 104448: csc[4][4][32] floats
#define SMEM_BYTES (SM_CSC + 4 * 4 * 32 * 4)

// ---------------- PTX helpers (compute_103-safe subset) ----------------
__device__ __forceinline__ uint32_t smem_to_u32(const void* p) {
    uint32_t a;
    asm("{ .reg .u64 t; cvta.to.shared.u64 t, %1; cvt.u32.u64 %0, t; }"
        : "=r"(a) : "l"(p));
    return a;
}
__device__ __forceinline__ void ldsm4(uint32_t* r, uint32_t addr) {
    asm volatile("ldmatrix.sync.aligned.m8n8.x4.shared.b16 {%0,%1,%2,%3}, [%4];"
                 : "=r"(r[0]), "=r"(r[1]), "=r"(r[2]), "=r"(r[3]) : "r"(addr));
}
__device__ __forceinline__ void mma16832(float* d, const uint32_t* a, const uint32_t* b) {
    asm volatile(
        "mma.sync.aligned.m16n8k32.row.col.f32.e4m3.e4m3.f32 "
        "{%0,%1,%2,%3}, {%4,%5,%6,%7}, {%8,%9}, {%0,%1,%2,%3};"
        : "+f"(d[0]), "+f"(d[1]), "+f"(d[2]), "+f"(d[3])
        : "r"(a[0]), "r"(a[1]), "r"(a[2]), "r"(a[3]), "r"(b[0]), "r"(b[1]));
}
__device__ __forceinline__ void cp16(uint32_t smaddr, const void* gptr) {
    asm volatile("cp.async.cg.shared.global [%0], [%1], 16;"
                 :: "r"(smaddr), "l"(gptr) : "memory");
}
#define CP_COMMIT() asm volatile("cp.async.commit_group;" ::: "memory")
template <int N>
__device__ __forceinline__ void cp_wait() {
    asm volatile("cp.async.wait_group %0;" :: "n"(N) : "memory");
}
__device__ __forceinline__ void bar4(int id) {       // 4-warp named barrier
    asm volatile("bar.sync %0, 128;" :: "r"(id) : "memory");
}
__device__ __forceinline__ float ex2(float x) {
    float r;
    asm("ex2.approx.f32 %0, %1;" : "=f"(r) : "f"(x));
    return r;
}

// Async-copy one 128x256-byte fp8 tile into smem (2048 16B chunks, 512 thr).
__device__ __forceinline__ void cp_tile(uint32_t smb, int smoff, int row0) {
    const int tid = threadIdx.x;
    #pragma unroll
    for (int it = 0; it < 4; ++it) {
        int idx = it * NTH + tid;
        int r = idx >> 4;
        int c = idx & 15;
        cp16(smb + smoff + r * SMS_B + c * 16,
             g_Z + (size_t)(row0 + r) * DDIM + c * 16);
    }
}

// ---------------------------------------------------------------------------
// Kernel A: normalize, scale by sqrt(2*log2e), quantize e4m3; fused pos dot.
// One warp per pair (i, i+N). pos from raw fp32 (unscaled, exact).
// ---------------------------------------------------------------------------
__global__ __launch_bounds__(256) void norm_kernel(const float* __restrict__ zis,
                                                   const float* __restrict__ zjs)
{
    const int wid = threadIdx.x >> 5, lane = threadIdx.x & 31;
    const int i = blockIdx.x * 8 + wid;                 // pair index 0..4095
    const float* sj = zjs + (size_t)i * DDIM;
    const float* si = zis + (size_t)i * DDIM;

    float4 j0 = reinterpret_cast<const float4*>(sj)[lane];
    float4 j1 = reinterpret_cast<const float4*>(sj)[lane + 32];
    float4 i0 = reinterpret_cast<const float4*>(si)[lane];
    float4 i1 = reinterpret_cast<const float4*>(si)[lane + 32];

    float ssj = j0.x*j0.x + j0.y*j0.y + j0.z*j0.z + j0.w*j0.w
              + j1.x*j1.x + j1.y*j1.y + j1.z*j1.z + j1.w*j1.w;
    float ssi = i0.x*i0.x + i0.y*i0.y + i0.z*i0.z + i0.w*i0.w
              + i1.x*i1.x + i1.y*i1.y + i1.z*i1.z + i1.w*i1.w;
    float dot = j0.x*i0.x + j0.y*i0.y + j0.z*i0.z + j0.w*i0.w
              + j1.x*i1.x + j1.y*i1.y + j1.z*i1.z + j1.w*i1.w;
    #pragma unroll
    for (int o = 16; o > 0; o >>= 1) {
        ssj += __shfl_xor_sync(0xffffffffu, ssj, o);
        ssi += __shfl_xor_sync(0xffffffffu, ssi, o);
        dot += __shfl_xor_sync(0xffffffffu, dot, o);
    }
    float invj = 1.0f / fmaxf(sqrtf(ssj), 1e-8f);
    float invi = 1.0f / fmaxf(sqrtf(ssi), 1e-8f);
    if (lane == 0) {
        float p = 2.0f * dot * invi * invj;
        g_pos[i] = p;
        g_pos[i + N_HALF] = p;
    }
    const float qj = invj * SQRT_L2E2;
    const float qi = invi * SQRT_L2E2;
    uint32_t* dj = reinterpret_cast<uint32_t*>(g_Z + (size_t)i * DDIM);
    uint32_t* di = reinterpret_cast<uint32_t*>(g_Z + (size_t)(i + N_HALF) * DDIM);
    __nv_fp8x4_e4m3 pj0(make_float4(j0.x*qj, j0.y*qj, j0.z*qj, j0.w*qj));
    __nv_fp8x4_e4m3 pj1(make_float4(j1.x*qj, j1.y*qj, j1.z*qj, j1.w*qj));
    __nv_fp8x4_e4m3 pi0(make_float4(i0.x*qi, i0.y*qi, i0.z*qi, i0.w*qi));
    __nv_fp8x4_e4m3 pi1(make_float4(i1.x*qi, i1.y*qi, i1.z*qi, i1.w*qi));
    dj[lane]      = *reinterpret_cast<uint32_t*>(&pj0);
    dj[lane + 32] = *reinterpret_cast<uint32_t*>(&pj1);
    di[lane]      = *reinterpret_cast<uint32_t*>(&pi0);
    di[lane + 32] = *reinterpret_cast<uint32_t*>(&pi1);
}

// ---------------------------------------------------------------------------
// Kernel B: strip of up to 4 tiles per CTA. 512 threads, warps 4(M) x 4(N),
// warp tile 32x32. FP8 k-loop: 8 steps of k=32, 4 ldsm + 8 mma per step.
// ---------------------------------------------------------------------------
__global__ __launch_bounds__(NTH) void simexp_kernel()
{
    const int I = blockIdx.y;
    const int J0 = I + STRIP * blockIdx.x;
    if (J0 >= NT64) return;
    const int nt = min(STRIP, NT64 - J0);

    extern __shared__ char sm[];
    const uint32_t smb = smem_to_u32(sm);
    const int tid = threadIdx.x;
    const int wid = tid >> 5;
    const int lane = tid & 31;
    const int wm = wid >> 2;              // 0..3 (M)
    const int wn = wid & 3;               // 0..3 (N)
    const int rb = I * RT;

    // fp8 ldmatrix addressing (b16 view; 4 consecutive fp8 per reg):
    //  A x4: lanes 0-7 rows+0/kB0 | 8-15 rows+8/kB0 | 16-23 rows+0/kB16 | 24-31 rows+8/kB16
    //  B x4: lanes 0-7 n+0/kB0    | 8-15 n+0/kB16   | 16-23 n+8/kB0    | 24-31 n+8/kB16
    const int a_row  = wm * 32 + (lane & 7) + ((lane >> 3) & 1) * 8;
    const int a_kadB = (lane >> 4) * 16;
    const int b_row  = wn * 32 + (lane & 7) + ((lane >> 4) & 1) * 8;
    const int b_kadB = ((lane >> 3) & 1) * 16;

    const uint32_t smA = smb + SM_A;
    float* csc = reinterpret_cast<float*>(sm + SM_CSC);   // [4 wn][4 wm][32]

    // Prologue: A + (B of first tile, unless diagonal)
    cp_tile(smb, SM_A, rb);
    if (J0 != I) cp_tile(smb, SM_B0, J0 * RT);
    CP_COMMIT();

    const int qrow = lane >> 2;
    const int drow0 = rb + wm * 32 + qrow;

    float rsum[4];                          // strip-persistent row sums
    #pragma unroll
    for (int q = 0; q < 4; ++q) rsum[q] = 0.f;

    int buf = 0;
    for (int s = 0; s < nt; ++s) {
        const int J = J0 + s;
        const int cb = J * RT;
        const bool diagT = (J == I);

        cp_wait<0>();
        __syncthreads();                    // single CTA sync per tile

        if (s + 1 < nt) {
            cp_tile(smb, (buf ^ 1) ? SM_B1 : SM_B0, (J + 1) * RT);
            CP_COMMIT();
        }

        const uint32_t smB = diagT ? smA : (smb + (buf ? SM_B1 : SM_B0));

        float d[2][4][4];
        #pragma unroll
        for (int mf = 0; mf < 2; ++mf)
            #pragma unroll
            for (int nf = 0; nf < 4; ++nf)
                #pragma unroll
                for (int e = 0; e < 4; ++e) d[mf][nf][e] = 0.f;

        #pragma unroll
        for (int ks = 0; ks < DDIM / 32; ++ks) {
            const int k0b = ks * 32;        // byte offset of this k-chunk
            uint32_t a[2][4];
            #pragma unroll
            for (int mf = 0; mf < 2; ++mf)
                ldsm4(a[mf], smA + (uint32_t)(a_row + mf * 16) * SMS_B
                                 + (uint32_t)(k0b + a_kadB));
            uint32_t b[4][2];
            #pragma unroll
            for (int nh = 0; nh < 2; ++nh) {
                uint32_t r4[4];
                ldsm4(r4, smB + (uint32_t)(b_row + nh * 16) * SMS_B
                              + (uint32_t)(k0b + b_kadB));
                b[2*nh][0] = r4[0]; b[2*nh][1] = r4[1];
                b[2*nh+1][0] = r4[2]; b[2*nh+1][1] = r4[3];
            }
            #pragma unroll
            for (int mf = 0; mf < 2; ++mf)
                #pragma unroll
                for (int nf = 0; nf < 4; ++nf)
                    mma16832(d[mf][nf], a[mf], b[nf]);
        }

        // Epilogue: e = ex2(d) = exp(2*sim) (scale folded into Z).
        const int dcol0 = cb + wn * 32 + 2 * (lane & 3);
        float csum[8];
        #pragma unroll
        for (int q = 0; q < 8; ++q) csum[q] = 0.f;

        #pragma unroll
        for (int mf = 0; mf < 2; ++mf) {
            const int r0 = drow0 + mf * 16;
            #pragma unroll
            for (int nf = 0; nf < 4; ++nf) {
                const int c0 = dcol0 + nf * 8;
                float e0 = ex2(d[mf][nf][0]);
                float e1 = ex2(d[mf][nf][1]);
                float e2 = ex2(d[mf][nf][2]);
                float e3 = ex2(d[mf][nf][3]);
                if (diagT) {
                    if (c0     == r0    ) e0 = 0.f;
                    if (c0 + 1 == r0    ) e1 = 0.f;
                    if (c0     == r0 + 8) e2 = 0.f;
                    if (c0 + 1 == r0 + 8) e3 = 0.f;
                }
                rsum[mf*2]   += e0 + e1;
                rsum[mf*2+1] += e2 + e3;
                csum[nf*2]   += e0 + e2;
                csum[nf*2+1] += e1 + e3;
            }
        }

        if (!diagT) {
            #pragma unroll
            for (int q = 0; q < 8; ++q) {
                float w = csum[q];
                w += __shfl_xor_sync(0xffffffffu, w, 4);
                w += __shfl_xor_sync(0xffffffffu, w, 8);
                w += __shfl_xor_sync(0xffffffffu, w, 16);
                csum[q] = w;
            }
            float* my = csc + (wn * 4 + wm) * 32;
            if (lane < 4) {
                #pragma unroll
                for (int nf = 0; nf < 4; ++nf)
                    #pragma unroll
                    for (int e2 = 0; e2 < 2; ++e2)
                        my[nf * 8 + 2 * lane + e2] = csum[nf*2+e2];
            }
            bar4(1 + wn);
            if (wm == 0) {
                float v = csc[(wn*4+0)*32 + lane] + csc[(wn*4+1)*32 + lane]
                        + csc[(wn*4+2)*32 + lane] + csc[(wn*4+3)*32 + lane];
                g_spart[I][cb + wn * 32 + lane] = v;
            }
        }

        if (s + 1 < nt) buf ^= 1;
    }

    // Strip end: reduce row sums (quad lanes share rows) and write slot J0.
    #pragma unroll
    for (int q = 0; q < 4; ++q) {
        float v = rsum[q];
        v += __shfl_xor_sync(0xffffffffu, v, 1);
        v += __shfl_xor_sync(0xffffffffu, v, 2);
        rsum[q] = v;
    }
    __syncthreads();                        // all mma reads of smA done
    float* redR = reinterpret_cast<float*>(sm);          // [4 wn][128]
    if ((lane & 3) == 0) {
        #pragma unroll
        for (int mf = 0; mf < 2; ++mf)
            #pragma unroll
            for (int h = 0; h < 2; ++h)
                redR[wn * RT + wm * 32 + mf * 16 + h * 8 + qrow] = rsum[mf*2+h];
    }
    __syncthreads();
    if (tid < RT) {
        float rs = redR[tid] + redR[RT+tid] + redR[2*RT+tid] + redR[3*RT+tid];
        g_spart[J0][rb + tid] = rs;
    }
}

// ---------------------------------------------------------------------------
// Kernel D: merged loss (threadfence reduction; deterministic).
// ---------------------------------------------------------------------------
__global__ __launch_bounds__(256) void loss_kernel(float* __restrict__ out)
{
    __shared__ float red[8];
    __shared__ bool amLast;
    const int tid = threadIdx.x;
    const int i = blockIdx.x * 256 + tid;       // exactly 8192 threads
    float s = 0.f;
    #pragma unroll 8
    for (int t = 0; t < NT64; ++t)
        s += g_spart[t][i];
    float acc = __logf(s) - g_pos[i];
    #pragma unroll
    for (int o = 16; o > 0; o >>= 1)
        acc += __shfl_xor_sync(0xffffffffu, acc, o);
    if ((tid & 31) == 0) red[tid >> 5] = acc;
    __syncthreads();
    if (tid == 0) {
        float t = 0.f;
        #pragma unroll
        for (int w = 0; w < 8; ++w) t += red[w];
        g_red[blockIdx.x] = t;
        __threadfence();
        unsigned int v = atomicAdd(&g_ctr, 1u);
        amLast = (v == 31u);
    }
    __syncthreads();
    if (amLast && tid < 32) {
        float v = g_red[tid];
        #pragma unroll
        for (int o = 16; o > 0; o >>= 1)
            v += __shfl_xor_sync(0xffffffffu, v, o);
        if (tid == 0) {
            out[0] = v / (float)M_TOTAL;
            g_ctr = 0u;                     // reset for next graph replay
        }
    }
}

// ---------------------------------------------------------------------------
extern "C" void kernel_launch(void* const* d_in, const int* in_sizes, int n_in,
                              void* d_out, int out_size)
{
    const float* zis = (const float*)d_in[0];
    const float* zjs = (const float*)d_in[1];
    float* out = (float*)d_out;

    norm_kernel<<<N_HALF / 8, 256>>>(zis, zjs);

    cudaFuncSetAttribute(simexp_kernel,
                         cudaFuncAttributeMaxDynamicSharedMemorySize, SMEM_BYTES);
    simexp_kernel<<<dim3(16, NT64), NTH, SMEM_BYTES>>>();

    loss_kernel<<<32, 256>>>(out);
}

// round 13
// speedup vs baseline: 1.0056x; 1.0056x over previous
#include <cuda_runtime.h>
#include <cuda_bf16.h>
#include <cstdint>
#include <math.h>

// NTXentLoss via mma.sync (HMMA) bf16 GEMM, symmetric upper-triangular tiles.
// Round 13: persistent simexp (148 CTAs, dynamic LPT strip queue via atomic
// counter — deterministic since every (slot,row) partial is written once with
// an assignment-independent value), bf16 (fp8 proved rate-neutral), 2-pair
// norm for ILP. Core mma config = round 8 (best measured).

#define M_TOTAL 8192
#define N_HALF  4096
#define DDIM    256
#define RT      128
#define NT64    (M_TOTAL / RT)           // 64 tile blocks
#define NSTRIPS 544                      // 496 len-4 + 16 len-3 + 16 len-2 + 16 len-1
#define NFULL   496
#define SMS     (DDIM + 8)               // smem row stride in bf16 (pad)
#define SMS_B   (SMS * 2)                // 528 bytes
#define SQRT_L2E2 1.6986441f             // sqrt(2/ln2); dot = 2*log2e*sim
#define GRID_P  148                      // persistent CTAs (1 per SM)

// Scratch (__device__ globals: allocation-free rule)
__device__ __nv_bfloat16 g_Z[M_TOTAL * DDIM];       // normalized*SQRT_L2E2, bf16
__device__ float g_pos[M_TOTAL];                    // 2*sim[i, pair] (fp32)
__device__ float g_spart[NT64][M_TOTAL];            // partial sums, slot-unique
__device__ float g_red[32];                         // loss block partials
__device__ unsigned int g_ctr;                      // loss completion counter
__device__ unsigned int g_work;                     // strip work counter

// smem layout (bytes)
#define SM_A    0
#define SM_B0   (RT * SMS_B)             // 67584
#define SM_B1   (2 * RT * SMS_B)         // 135168
#define SM_CSC  (3 * RT * SMS_B)         // 202752: csc[4][2][32] floats
#define SMEM_BYTES (SM_CSC + 4 * 2 * 32 * 4)

// ---------------- PTX helpers (compute_103-safe subset) ----------------
__device__ __forceinline__ uint32_t smem_to_u32(const void* p) {
    uint32_t a;
    asm("{ .reg .u64 t; cvta.to.shared.u64 t, %1; cvt.u32.u64 %0, t; }"
        : "=r"(a) : "l"(p));
    return a;
}
__device__ __forceinline__ void ldsm4(uint32_t* r, uint32_t addr) {
    asm volatile("ldmatrix.sync.aligned.m8n8.x4.shared.b16 {%0,%1,%2,%3}, [%4];"
                 : "=r"(r[0]), "=r"(r[1]), "=r"(r[2]), "=r"(r[3]) : "r"(addr));
}
__device__ __forceinline__ void mma16816(float* d, const uint32_t* a, const uint32_t* b) {
    asm volatile(
        "mma.sync.aligned.m16n8k16.row.col.f32.bf16.bf16.f32 "
        "{%0,%1,%2,%3}, {%4,%5,%6,%7}, {%8,%9}, {%0,%1,%2,%3};"
        : "+f"(d[0]), "+f"(d[1]), "+f"(d[2]), "+f"(d[3])
        : "r"(a[0]), "r"(a[1]), "r"(a[2]), "r"(a[3]), "r"(b[0]), "r"(b[1]));
}
__device__ __forceinline__ void cp16(uint32_t smaddr, const void* gptr) {
    asm volatile("cp.async.cg.shared.global [%0], [%1], 16;"
                 :: "r"(smaddr), "l"(gptr) : "memory");
}
#define CP_COMMIT() asm volatile("cp.async.commit_group;" ::: "memory")
template <int N>
__device__ __forceinline__ void cp_wait() {
    asm volatile("cp.async.wait_group %0;" :: "n"(N) : "memory");
}
__device__ __forceinline__ void barpair(int id) {    // 2-warp named barrier
    asm volatile("bar.sync %0, 64;" :: "r"(id) : "memory");
}
__device__ __forceinline__ float ex2(float x) {
    float r;
    asm("ex2.approx.f32 %0, %1;" : "=f"(r) : "f"(x));
    return r;
}

// Async-copy one full 128x256 bf16 tile into smem (4096 16B chunks, 256 thr).
__device__ __forceinline__ void cp_tile(uint32_t smb, int smoff, int row0) {
    const int tid = threadIdx.x;
    #pragma unroll
    for (int it = 0; it < 16; ++it) {
        int idx = it * 256 + tid;
        int r = idx >> 5;
        int c = idx & 31;
        cp16(smb + smoff + r * SMS_B + c * 16,
             g_Z + (size_t)(row0 + r) * DDIM + c * 8);
    }
}

// Strip decode, LPT order: s in [0,496) -> len-4 strips (I asc, c asc);
// s in [496,544) -> shorts: len3 (I=1 mod 4), len2 (I=2 mod 4), len1 (I=3 mod 4).
__device__ __forceinline__ void decode_strip(int s, int& I, int& J0, int& len) {
    if (s < NFULL) {
        int i = 0;
        for (;;) {
            int cnt = (NT64 - i) >> 2;
            if (s < cnt) break;
            s -= cnt;
            ++i;
        }
        I = i;
        J0 = i + 4 * s;
        len = 4;
    } else {
        int idx = s - NFULL;
        int grp = idx >> 4;                  // 0: len3, 1: len2, 2: len1
        int k = idx & 15;
        len = 3 - grp;
        I = (1 + grp) + 4 * k;
        J0 = I + (((NT64 - I) >> 2) << 2);
    }
}

// ---------------------------------------------------------------------------
// Kernel A: normalize, scale by sqrt(2*log2e), bf16 quantize; fused pos dot.
// Two pairs per warp (ILP). Also resets the simexp work counter.
// ---------------------------------------------------------------------------
__global__ __launch_bounds__(256) void norm_kernel(const float* __restrict__ zis,
                                                   const float* __restrict__ zjs)
{
    if (blockIdx.x == 0 && threadIdx.x == 0) g_work = 0u;

    const int wid = threadIdx.x >> 5, lane = threadIdx.x & 31;
    const int ibase = blockIdx.x * 16 + wid * 2;        // 256 blocks x 8 warps x 2
    #pragma unroll
    for (int u = 0; u < 2; ++u) {
        const int i = ibase + u;
        const float* sj = zjs + (size_t)i * DDIM;
        const float* si = zis + (size_t)i * DDIM;

        float4 j0 = reinterpret_cast<const float4*>(sj)[lane];
        float4 j1 = reinterpret_cast<const float4*>(sj)[lane + 32];
        float4 i0 = reinterpret_cast<const float4*>(si)[lane];
        float4 i1 = reinterpret_cast<const float4*>(si)[lane + 32];

        float ssj = j0.x*j0.x + j0.y*j0.y + j0.z*j0.z + j0.w*j0.w
                  + j1.x*j1.x + j1.y*j1.y + j1.z*j1.z + j1.w*j1.w;
        float ssi = i0.x*i0.x + i0.y*i0.y + i0.z*i0.z + i0.w*i0.w
                  + i1.x*i1.x + i1.y*i1.y + i1.z*i1.z + i1.w*i1.w;
        float dot = j0.x*i0.x + j0.y*i0.y + j0.z*i0.z + j0.w*i0.w
                  + j1.x*i1.x + j1.y*i1.y + j1.z*i1.z + j1.w*i1.w;
        #pragma unroll
        for (int o = 16; o > 0; o >>= 1) {
            ssj += __shfl_xor_sync(0xffffffffu, ssj, o);
            ssi += __shfl_xor_sync(0xffffffffu, ssi, o);
            dot += __shfl_xor_sync(0xffffffffu, dot, o);
        }
        float invj = 1.0f / fmaxf(sqrtf(ssj), 1e-8f);
        float invi = 1.0f / fmaxf(sqrtf(ssi), 1e-8f);
        if (lane == 0) {
            float p = 2.0f * dot * invi * invj;
            g_pos[i] = p;
            g_pos[i + N_HALF] = p;
        }
        const float qj = invj * SQRT_L2E2;
        const float qi = invi * SQRT_L2E2;
        __nv_bfloat162* dj = reinterpret_cast<__nv_bfloat162*>(g_Z + (size_t)i * DDIM);
        __nv_bfloat162* di = reinterpret_cast<__nv_bfloat162*>(g_Z + (size_t)(i + N_HALF) * DDIM);
        dj[lane*2+0]    = __floats2bfloat162_rn(j0.x*qj, j0.y*qj);
        dj[lane*2+1]    = __floats2bfloat162_rn(j0.z*qj, j0.w*qj);
        dj[64+lane*2+0] = __floats2bfloat162_rn(j1.x*qj, j1.y*qj);
        dj[64+lane*2+1] = __floats2bfloat162_rn(j1.z*qj, j1.w*qj);
        di[lane*2+0]    = __floats2bfloat162_rn(i0.x*qi, i0.y*qi);
        di[lane*2+1]    = __floats2bfloat162_rn(i0.z*qi, i0.w*qi);
        di[64+lane*2+0] = __floats2bfloat162_rn(i1.x*qi, i1.y*qi);
        di[64+lane*2+1] = __floats2bfloat162_rn(i1.z*qi, i1.w*qi);
    }
}

// ---------------------------------------------------------------------------
// Kernel B: persistent; 148 CTAs pull strips from g_work. Round-8 mma core:
// 256 threads, warps 2(M) x 4(N), warp tile 64x32, A resident per strip,
// B double-buffered cp.async, 1 CTA sync per tile, bare-ex2 epilogue.
// ---------------------------------------------------------------------------
__global__ __launch_bounds__(256) void simexp_kernel()
{
    extern __shared__ char sm[];
    __shared__ int s_job;
    const uint32_t smb = smem_to_u32(sm);
    const int tid = threadIdx.x;
    const int wid = tid >> 5;
    const int lane = tid & 31;
    const int wm = wid >> 2;              // 0..1 (M)
    const int wn = wid & 3;               // 0..3 (N)

    const int a_row = wm * 64 + (lane & 7) + ((lane >> 3) & 1) * 8;
    const int a_kad = (lane >> 4) * 8;
    const int b_row = wn * 32 + (lane & 7) + ((lane >> 4) & 1) * 8;
    const int b_kad = ((lane >> 3) & 1) * 8;

    const uint32_t smA = smb + SM_A;
    float* csc = reinterpret_cast<float*>(sm + SM_CSC);   // [4 wn][2 wm][32]
    const int qrow = lane >> 2;

    for (;;) {
        if (tid == 0) s_job = (int)atomicAdd(&g_work, 1u);
        __syncthreads();
        const int job = s_job;
        if (job >= NSTRIPS) break;

        int I, J0, nt;
        decode_strip(job, I, J0, nt);
        const int rb = I * RT;
        const int drow0 = rb + wm * 64 + qrow;

        // Prologue: A + (B of first tile, unless diagonal)
        cp_tile(smb, SM_A, rb);
        if (J0 != I) cp_tile(smb, SM_B0, J0 * RT);
        CP_COMMIT();

        float rsum[8];                      // strip-persistent row sums
        #pragma unroll
        for (int q = 0; q < 8; ++q) rsum[q] = 0.f;

        int buf = 0;
        for (int s = 0; s < nt; ++s) {
            const int J = J0 + s;
            const int cb = J * RT;
            const bool diagT = (J == I);

            cp_wait<0>();
            __syncthreads();                // single CTA sync per tile

            if (s + 1 < nt) {
                cp_tile(smb, (buf ^ 1) ? SM_B1 : SM_B0, (J + 1) * RT);
                CP_COMMIT();
            }

            const uint32_t smB = diagT ? smA : (smb + (buf ? SM_B1 : SM_B0));

            float d[4][4][4];
            #pragma unroll
            for (int mf = 0; mf < 4; ++mf)
                #pragma unroll
                for (int nf = 0; nf < 4; ++nf)
                    #pragma unroll
                    for (int e = 0; e < 4; ++e) d[mf][nf][e] = 0.f;

            #pragma unroll
            for (int ks = 0; ks < DDIM / 16; ++ks) {
                const int k0 = ks * 16;
                uint32_t a[4][4];
                #pragma unroll
                for (int mf = 0; mf < 4; ++mf)
                    ldsm4(a[mf], smA + (uint32_t)(a_row + mf * 16) * SMS_B
                                     + (uint32_t)(k0 + a_kad) * 2);
                uint32_t b[4][2];
                #pragma unroll
                for (int nh = 0; nh < 2; ++nh) {
                    uint32_t r4[4];
                    ldsm4(r4, smB + (uint32_t)(b_row + nh * 16) * SMS_B
                                  + (uint32_t)(k0 + b_kad) * 2);
                    b[2*nh][0] = r4[0]; b[2*nh][1] = r4[1];
                    b[2*nh+1][0] = r4[2]; b[2*nh+1][1] = r4[3];
                }
                #pragma unroll
                for (int mf = 0; mf < 4; ++mf)
                    #pragma unroll
                    for (int nf = 0; nf < 4; ++nf)
                        mma16816(d[mf][nf], a[mf], b[nf]);
            }

            // Epilogue: e = ex2(d) = exp(2*sim) (scale folded into Z).
            const int dcol0 = cb + wn * 32 + 2 * (lane & 3);
            float csum[8];
            #pragma unroll
            for (int q = 0; q < 8; ++q) csum[q] = 0.f;

            #pragma unroll
            for (int mf = 0; mf < 4; ++mf) {
                const int r0 = drow0 + mf * 16;
                #pragma unroll
                for (int nf = 0; nf < 4; ++nf) {
                    const int c0 = dcol0 + nf * 8;
                    float e0 = ex2(d[mf][nf][0]);
                    float e1 = ex2(d[mf][nf][1]);
                    float e2 = ex2(d[mf][nf][2]);
                    float e3 = ex2(d[mf][nf][3]);
                    if (diagT) {
                        if (c0     == r0    ) e0 = 0.f;
                        if (c0 + 1 == r0    ) e1 = 0.f;
                        if (c0     == r0 + 8) e2 = 0.f;
                        if (c0 + 1 == r0 + 8) e3 = 0.f;
                    }
                    rsum[mf*2]   += e0 + e1;
                    rsum[mf*2+1] += e2 + e3;
                    csum[nf*2]   += e0 + e2;
                    csum[nf*2+1] += e1 + e3;
                }
            }

            if (!diagT) {
                #pragma unroll
                for (int q = 0; q < 8; ++q) {
                    float w = csum[q];
                    w += __shfl_xor_sync(0xffffffffu, w, 4);
                    w += __shfl_xor_sync(0xffffffffu, w, 8);
                    w += __shfl_xor_sync(0xffffffffu, w, 16);
                    csum[q] = w;
                }
                float* my = csc + (wn * 2 + wm) * 32;
                if (lane < 4) {
                    #pragma unroll
                    for (int nf = 0; nf < 4; ++nf)
                        #pragma unroll
                        for (int e2 = 0; e2 < 2; ++e2)
                            my[nf * 8 + 2 * lane + e2] = csum[nf*2+e2];
                }
                barpair(1 + wn);
                if (wm == 1) {
                    float v = csc[(wn*2+0)*32 + lane] + csc[(wn*2+1)*32 + lane];
                    g_spart[I][cb + wn * 32 + lane] = v;
                }
            }

            if (s + 1 < nt) buf ^= 1;
        }

        // Strip end: reduce row sums and write slot J0.
        #pragma unroll
        for (int q = 0; q < 8; ++q) {
            float v = rsum[q];
            v += __shfl_xor_sync(0xffffffffu, v, 1);
            v += __shfl_xor_sync(0xffffffffu, v, 2);
            rsum[q] = v;
        }
        __syncthreads();                    // all mma reads of smA done
        float* redR = reinterpret_cast<float*>(sm);      // [4 wn][128]
        if ((lane & 3) == 0) {
            #pragma unroll
            for (int mf = 0; mf < 4; ++mf)
                #pragma unroll
                for (int h = 0; h < 2; ++h)
                    redR[wn * RT + wm * 64 + mf * 16 + h * 8 + qrow] = rsum[mf*2+h];
        }
        __syncthreads();
        if (tid < RT) {
            float rs = redR[tid] + redR[RT+tid] + redR[2*RT+tid] + redR[3*RT+tid];
            g_spart[J0][rb + tid] = rs;
        }
        __syncthreads();                    // redR reads done before next strip
    }
}

// ---------------------------------------------------------------------------
// Kernel D: merged loss (threadfence reduction; deterministic).
// Unwritten g_spart slots are never touched -> remain 0 (BSS) every replay.
// ---------------------------------------------------------------------------
__global__ __launch_bounds__(256) void loss_kernel(float* __restrict__ out)
{
    __shared__ float red[8];
    __shared__ bool amLast;
    const int tid = threadIdx.x;
    const int i = blockIdx.x * 256 + tid;       // exactly 8192 threads
    float s = 0.f;
    #pragma unroll 8
    for (int t = 0; t < NT64; ++t)
        s += g_spart[t][i];
    float acc = __logf(s) - g_pos[i];
    #pragma unroll
    for (int o = 16; o > 0; o >>= 1)
        acc += __shfl_xor_sync(0xffffffffu, acc, o);
    if ((tid & 31) == 0) red[tid >> 5] = acc;
    __syncthreads();
    if (tid == 0) {
        float t = 0.f;
        #pragma unroll
        for (int w = 0; w < 8; ++w) t += red[w];
        g_red[blockIdx.x] = t;
        __threadfence();
        unsigned int v = atomicAdd(&g_ctr, 1u);
        amLast = (v == 31u);
    }
    __syncthreads();
    if (amLast && tid < 32) {
        float v = g_red[tid];
        #pragma unroll
        for (int o = 16; o > 0; o >>= 1)
            v += __shfl_xor_sync(0xffffffffu, v, o);
        if (tid == 0) {
            out[0] = v / (float)M_TOTAL;
            g_ctr = 0u;                     // reset for next graph replay
        }
    }
}

// ---------------------------------------------------------------------------
extern "C" void kernel_launch(void* const* d_in, const int* in_sizes, int n_in,
                              void* d_out, int out_size)
{
    const float* zis = (const float*)d_in[0];
    const float* zjs = (const float*)d_in[1];
    float* out = (float*)d_out;

    norm_kernel<<<N_HALF / 16, 256>>>(zis, zjs);

    cudaFuncSetAttribute(simexp_kernel,
                         cudaFuncAttributeMaxDynamicSharedMemorySize, SMEM_BYTES);
    simexp_kernel<<<GRID_P, 256, SMEM_BYTES>>>();

    loss_kernel<<<32, 256>>>(out);
}

// round 14
// speedup vs baseline: 1.0537x; 1.0478x over previous
#include <cuda_runtime.h>
#include <cuda_bf16.h>
#include <cuda_fp8.h>
#include <cstdint>
#include <math.h>

// NTXentLoss via mma.sync FP8 (e4m3) GEMM, symmetric upper-triangular tiles.
// Round 14: round-8 structure (best measured: static grid, strip-4, 256 thr,
// 2x4 warps) but FP8 tiles -> 105 KB smem -> 2 CTAs/SM co-resident: one CTA's
// epilogue/prologue overlaps the other's HMMA issue, and work quantum halves.
// Z = normalize(reps)*sqrt(2*log2e) in e4m3; epilogue is bare ex2; pos fp32.

#define M_TOTAL 8192
#define N_HALF  4096
#define DDIM    256
#define RT      128
#define NT64    (M_TOTAL / RT)           // 64 tile blocks
#define STRIP   4
#define SMS_B   272                      // fp8 tile row stride: 256 B + 16 pad
#define SQRT_L2E2 1.6986441f             // sqrt(2/ln2); dot = 2*log2e*sim

// Scratch (__device__ globals: allocation-free rule)
__device__ uint8_t g_Z[M_TOTAL * DDIM];             // normalized*s, e4m3
__device__ float g_pos[M_TOTAL];                    // 2*sim[i, pair] (fp32)
__device__ float g_spart[NT64][M_TOTAL];            // partial sums, slot-unique
__device__ float g_red[32];                         // loss block partials
__device__ unsigned int g_ctr;                      // loss completion counter

// smem layout (bytes) — total ~105 KB -> 2 CTAs/SM
#define SM_A    0
#define SM_B0   (RT * SMS_B)             // 34816
#define SM_B1   (2 * RT * SMS_B)         // 69632
#define SM_CSC  (3 * RT * SMS_B)         // 104448: csc[4][2][32] floats
#define SMEM_BYTES (SM_CSC + 4 * 2 * 32 * 4)   // 105472

// ---------------- PTX helpers (compute_103-safe subset) ----------------
__device__ __forceinline__ uint32_t smem_to_u32(const void* p) {
    uint32_t a;
    asm("{ .reg .u64 t; cvta.to.shared.u64 t, %1; cvt.u32.u64 %0, t; }"
        : "=r"(a) : "l"(p));
    return a;
}
__device__ __forceinline__ void ldsm4(uint32_t* r, uint32_t addr) {
    asm volatile("ldmatrix.sync.aligned.m8n8.x4.shared.b16 {%0,%1,%2,%3}, [%4];"
                 : "=r"(r[0]), "=r"(r[1]), "=r"(r[2]), "=r"(r[3]) : "r"(addr));
}
__device__ __forceinline__ void mma16832(float* d, const uint32_t* a, const uint32_t* b) {
    asm volatile(
        "mma.sync.aligned.m16n8k32.row.col.f32.e4m3.e4m3.f32 "
        "{%0,%1,%2,%3}, {%4,%5,%6,%7}, {%8,%9}, {%0,%1,%2,%3};"
        : "+f"(d[0]), "+f"(d[1]), "+f"(d[2]), "+f"(d[3])
        : "r"(a[0]), "r"(a[1]), "r"(a[2]), "r"(a[3]), "r"(b[0]), "r"(b[1]));
}
__device__ __forceinline__ void cp16(uint32_t smaddr, const void* gptr) {
    asm volatile("cp.async.cg.shared.global [%0], [%1], 16;"
                 :: "r"(smaddr), "l"(gptr) : "memory");
}
#define CP_COMMIT() asm volatile("cp.async.commit_group;" ::: "memory")
template <int N>
__device__ __forceinline__ void cp_wait() {
    asm volatile("cp.async.wait_group %0;" :: "n"(N) : "memory");
}
__device__ __forceinline__ void barpair(int id) {    // 2-warp named barrier
    asm volatile("bar.sync %0, 64;" :: "r"(id) : "memory");
}
__device__ __forceinline__ float ex2(float x) {
    float r;
    asm("ex2.approx.f32 %0, %1;" : "=f"(r) : "f"(x));
    return r;
}

// Async-copy one 128x256-byte fp8 tile into smem (2048 16B chunks, 256 thr).
__device__ __forceinline__ void cp_tile(uint32_t smb, int smoff, int row0) {
    const int tid = threadIdx.x;
    #pragma unroll
    for (int it = 0; it < 8; ++it) {
        int idx = it * 256 + tid;
        int r = idx >> 4;
        int c = idx & 15;
        cp16(smb + smoff + r * SMS_B + c * 16,
             g_Z + (size_t)(row0 + r) * DDIM + c * 16);
    }
}

// ---------------------------------------------------------------------------
// Kernel A: normalize, scale by sqrt(2*log2e), e4m3 quantize; fused pos dot.
// Two pairs per warp (ILP). pos from raw fp32 (exact).
// ---------------------------------------------------------------------------
__global__ __launch_bounds__(256) void norm_kernel(const float* __restrict__ zis,
                                                   const float* __restrict__ zjs)
{
    const int wid = threadIdx.x >> 5, lane = threadIdx.x & 31;
    const int ibase = blockIdx.x * 16 + wid * 2;        // 256 blocks x 8 warps x 2
    #pragma unroll
    for (int u = 0; u < 2; ++u) {
        const int i = ibase + u;
        const float* sj = zjs + (size_t)i * DDIM;
        const float* si = zis + (size_t)i * DDIM;

        float4 j0 = reinterpret_cast<const float4*>(sj)[lane];
        float4 j1 = reinterpret_cast<const float4*>(sj)[lane + 32];
        float4 i0 = reinterpret_cast<const float4*>(si)[lane];
        float4 i1 = reinterpret_cast<const float4*>(si)[lane + 32];

        float ssj = j0.x*j0.x + j0.y*j0.y + j0.z*j0.z + j0.w*j0.w
                  + j1.x*j1.x + j1.y*j1.y + j1.z*j1.z + j1.w*j1.w;
        float ssi = i0.x*i0.x + i0.y*i0.y + i0.z*i0.z + i0.w*i0.w
                  + i1.x*i1.x + i1.y*i1.y + i1.z*i1.z + i1.w*i1.w;
        float dot = j0.x*i0.x + j0.y*i0.y + j0.z*i0.z + j0.w*i0.w
                  + j1.x*i1.x + j1.y*i1.y + j1.z*i1.z + j1.w*i1.w;
        #pragma unroll
        for (int o = 16; o > 0; o >>= 1) {
            ssj += __shfl_xor_sync(0xffffffffu, ssj, o);
            ssi += __shfl_xor_sync(0xffffffffu, ssi, o);
            dot += __shfl_xor_sync(0xffffffffu, dot, o);
        }
        float invj = 1.0f / fmaxf(sqrtf(ssj), 1e-8f);
        float invi = 1.0f / fmaxf(sqrtf(ssi), 1e-8f);
        if (lane == 0) {
            float p = 2.0f * dot * invi * invj;
            g_pos[i] = p;
            g_pos[i + N_HALF] = p;
        }
        const float qj = invj * SQRT_L2E2;
        const float qi = invi * SQRT_L2E2;
        uint32_t* dj = reinterpret_cast<uint32_t*>(g_Z + (size_t)i * DDIM);
        uint32_t* di = reinterpret_cast<uint32_t*>(g_Z + (size_t)(i + N_HALF) * DDIM);
        __nv_fp8x4_e4m3 pj0(make_float4(j0.x*qj, j0.y*qj, j0.z*qj, j0.w*qj));
        __nv_fp8x4_e4m3 pj1(make_float4(j1.x*qj, j1.y*qj, j1.z*qj, j1.w*qj));
        __nv_fp8x4_e4m3 pi0(make_float4(i0.x*qi, i0.y*qi, i0.z*qi, i0.w*qi));
        __nv_fp8x4_e4m3 pi1(make_float4(i1.x*qi, i1.y*qi, i1.z*qi, i1.w*qi));
        dj[lane]      = *reinterpret_cast<uint32_t*>(&pj0);
        dj[lane + 32] = *reinterpret_cast<uint32_t*>(&pj1);
        di[lane]      = *reinterpret_cast<uint32_t*>(&pi0);
        di[lane + 32] = *reinterpret_cast<uint32_t*>(&pi1);
    }
}

// ---------------------------------------------------------------------------
// Kernel B: strip of up to 4 upper-tri tiles per CTA. Static grid (16, 64):
// x = strip chunk, y = I; J0 = I + 4x (early exit if J0 >= 64).
// 256 threads, warps 2(M) x 4(N), warp tile 64x32, FP8 k-loop (8 x k=32).
// __launch_bounds__(256, 2): cap 128 regs so 2 CTAs co-reside per SM.
// ---------------------------------------------------------------------------
__global__ __launch_bounds__(256, 2) void simexp_kernel()
{
    const int I = blockIdx.y;
    const int J0 = I + STRIP * blockIdx.x;
    if (J0 >= NT64) return;
    const int nt = min(STRIP, NT64 - J0);

    extern __shared__ char sm[];
    const uint32_t smb = smem_to_u32(sm);
    const int tid = threadIdx.x;
    const int wid = tid >> 5;
    const int lane = tid & 31;
    const int wm = wid >> 2;              // 0..1 (M)
    const int wn = wid & 3;               // 0..3 (N)
    const int rb = I * RT;

    // fp8 ldmatrix addressing (b16 view; validated round 12):
    const int a_row  = wm * 64 + (lane & 7) + ((lane >> 3) & 1) * 8;
    const int a_kadB = (lane >> 4) * 16;
    const int b_row  = wn * 32 + (lane & 7) + ((lane >> 4) & 1) * 8;
    const int b_kadB = ((lane >> 3) & 1) * 16;

    const uint32_t smA = smb + SM_A;
    float* csc = reinterpret_cast<float*>(sm + SM_CSC);   // [4 wn][2 wm][32]

    // Prologue: A + (B of first tile, unless diagonal)
    cp_tile(smb, SM_A, rb);
    if (J0 != I) cp_tile(smb, SM_B0, J0 * RT);
    CP_COMMIT();

    const int qrow = lane >> 2;
    const int drow0 = rb + wm * 64 + qrow;

    float rsum[8];                          // strip-persistent row sums
    #pragma unroll
    for (int q = 0; q < 8; ++q) rsum[q] = 0.f;

    int buf = 0;
    for (int s = 0; s < nt; ++s) {
        const int J = J0 + s;
        const int cb = J * RT;
        const bool diagT = (J == I);

        cp_wait<0>();
        __syncthreads();                    // single CTA sync per tile

        if (s + 1 < nt) {
            cp_tile(smb, (buf ^ 1) ? SM_B1 : SM_B0, (J + 1) * RT);
            CP_COMMIT();
        }

        const uint32_t smB = diagT ? smA : (smb + (buf ? SM_B1 : SM_B0));

        float d[4][4][4];
        #pragma unroll
        for (int mf = 0; mf < 4; ++mf)
            #pragma unroll
            for (int nf = 0; nf < 4; ++nf)
                #pragma unroll
                for (int e = 0; e < 4; ++e) d[mf][nf][e] = 0.f;

        #pragma unroll
        for (int ks = 0; ks < DDIM / 32; ++ks) {
            const int k0b = ks * 32;        // byte offset of this k-chunk
            uint32_t a[4][4];
            #pragma unroll
            for (int mf = 0; mf < 4; ++mf)
                ldsm4(a[mf], smA + (uint32_t)(a_row + mf * 16) * SMS_B
                                 + (uint32_t)(k0b + a_kadB));
            #pragma unroll
            for (int nh = 0; nh < 2; ++nh) {
                uint32_t r4[4];
                ldsm4(r4, smB + (uint32_t)(b_row + nh * 16) * SMS_B
                              + (uint32_t)(k0b + b_kadB));
                uint32_t b0[2] = {r4[0], r4[1]};
                uint32_t b1[2] = {r4[2], r4[3]};
                #pragma unroll
                for (int mf = 0; mf < 4; ++mf) {
                    mma16832(d[mf][2*nh],     a[mf], b0);
                    mma16832(d[mf][2*nh + 1], a[mf], b1);
                }
            }
        }

        // Epilogue: e = ex2(d) = exp(2*sim) (scale folded into Z).
        const int dcol0 = cb + wn * 32 + 2 * (lane & 3);
        float csum[8];
        #pragma unroll
        for (int q = 0; q < 8; ++q) csum[q] = 0.f;

        #pragma unroll
        for (int mf = 0; mf < 4; ++mf) {
            const int r0 = drow0 + mf * 16;
            #pragma unroll
            for (int nf = 0; nf < 4; ++nf) {
                const int c0 = dcol0 + nf * 8;
                float e0 = ex2(d[mf][nf][0]);
                float e1 = ex2(d[mf][nf][1]);
                float e2 = ex2(d[mf][nf][2]);
                float e3 = ex2(d[mf][nf][3]);
                if (diagT) {
                    if (c0     == r0    ) e0 = 0.f;
                    if (c0 + 1 == r0    ) e1 = 0.f;
                    if (c0     == r0 + 8) e2 = 0.f;
                    if (c0 + 1 == r0 + 8) e3 = 0.f;
                }
                rsum[mf*2]   += e0 + e1;
                rsum[mf*2+1] += e2 + e3;
                csum[nf*2]   += e0 + e2;
                csum[nf*2+1] += e1 + e3;
            }
        }

        if (!diagT) {
            #pragma unroll
            for (int q = 0; q < 8; ++q) {
                float w = csum[q];
                w += __shfl_xor_sync(0xffffffffu, w, 4);
                w += __shfl_xor_sync(0xffffffffu, w, 8);
                w += __shfl_xor_sync(0xffffffffu, w, 16);
                csum[q] = w;
            }
            float* my = csc + (wn * 2 + wm) * 32;
            if (lane < 4) {
                #pragma unroll
                for (int nf = 0; nf < 4; ++nf)
                    #pragma unroll
                    for (int e2 = 0; e2 < 2; ++e2)
                        my[nf * 8 + 2 * lane + e2] = csum[nf*2+e2];
            }
            barpair(1 + wn);
            if (wm == 1) {
                float v = csc[(wn*2+0)*32 + lane] + csc[(wn*2+1)*32 + lane];
                g_spart[I][cb + wn * 32 + lane] = v;
            }
        }

        if (s + 1 < nt) buf ^= 1;
    }

    // Strip end: reduce row sums (quad lanes share rows) and write slot J0.
    #pragma unroll
    for (int q = 0; q < 8; ++q) {
        float v = rsum[q];
        v += __shfl_xor_sync(0xffffffffu, v, 1);
        v += __shfl_xor_sync(0xffffffffu, v, 2);
        rsum[q] = v;
    }
    __syncthreads();                        // all mma reads of smA done
    float* redR = reinterpret_cast<float*>(sm);          // [4 wn][128]
    if ((lane & 3) == 0) {
        #pragma unroll
        for (int mf = 0; mf < 4; ++mf)
            #pragma unroll
            for (int h = 0; h < 2; ++h)
                redR[wn * RT + wm * 64 + mf * 16 + h * 8 + qrow] = rsum[mf*2+h];
    }
    __syncthreads();
    if (tid < RT) {
        float rs = redR[tid] + redR[RT+tid] + redR[2*RT+tid] + redR[3*RT+tid];
        g_spart[J0][rb + tid] = rs;
    }
}

// ---------------------------------------------------------------------------
// Kernel D: merged loss (threadfence reduction; deterministic).
// ---------------------------------------------------------------------------
__global__ __launch_bounds__(256) void loss_kernel(float* __restrict__ out)
{
    __shared__ float red[8];
    __shared__ bool amLast;
    const int tid = threadIdx.x;
    const int i = blockIdx.x * 256 + tid;       // exactly 8192 threads
    float s = 0.f;
    #pragma unroll 8
    for (int t = 0; t < NT64; ++t)
        s += g_spart[t][i];
    float acc = __logf(s) - g_pos[i];
    #pragma unroll
    for (int o = 16; o > 0; o >>= 1)
        acc += __shfl_xor_sync(0xffffffffu, acc, o);
    if ((tid & 31) == 0) red[tid >> 5] = acc;
    __syncthreads();
    if (tid == 0) {
        float t = 0.f;
        #pragma unroll
        for (int w = 0; w < 8; ++w) t += red[w];
        g_red[blockIdx.x] = t;
        __threadfence();
        unsigned int v = atomicAdd(&g_ctr, 1u);
        amLast = (v == 31u);
    }
    __syncthreads();
    if (amLast && tid < 32) {
        float v = g_red[tid];
        #pragma unroll
        for (int o = 16; o > 0; o >>= 1)
            v += __shfl_xor_sync(0xffffffffu, v, o);
        if (tid == 0) {
            out[0] = v / (float)M_TOTAL;
            g_ctr = 0u;                     // reset for next graph replay
        }
    }
}

// ---------------------------------------------------------------------------
extern "C" void kernel_launch(void* const* d_in, const int* in_sizes, int n_in,
                              void* d_out, int out_size)
{
    const float* zis = (const float*)d_in[0];
    const float* zjs = (const float*)d_in[1];
    float* out = (float*)d_out;

    norm_kernel<<<N_HALF / 16, 256>>>(zis, zjs);

    cudaFuncSetAttribute(simexp_kernel,
                         cudaFuncAttributeMaxDynamicSharedMemorySize, SMEM_BYTES);
    simexp_kernel<<<dim3(16, NT64), 256, SMEM_BYTES>>>();

    loss_kernel<<<32, 256>>>(out);
}